// round 2
// baseline (speedup 1.0000x reference)
#include <cuda_runtime.h>

#define NB 128
#define NL 36
#define NV 36
#define ND 512
#define NKV 112
#define NQ 36
#define NH 512
#define G3 108
#define CKDIM 812   // D + KD
#define XDIM 624    // D + KV

// ---------------- scratch (device globals; no allocs allowed) ----------------
__device__ float g_csumW[NB * NL * G3];   // (sum_l context) @ Wih_u^T  per (b, view)
__device__ float g_gk[NB * NL * G3];      // knowledge @ Wih_k^T + bih
__device__ float g_w[NB * ND];            // per-iteration projection vector (scale folded)
__device__ float g_WihuT[ND * G3];
__device__ float g_WihkT[NKV * G3];
__device__ float g_WhhT[NQ * G3];
__device__ float g_W1T[NQ * NH];

// ---------------- weight transposes for coalesced access ----------------
__global__ void k_transpose(const float* __restrict__ Wih,
                            const float* __restrict__ Whh,
                            const float* __restrict__ W1) {
    int i = blockIdx.x * blockDim.x + threadIdx.x;
    if (i < ND * G3)  { int c = i / G3, o = i % G3; g_WihuT[i] = Wih[o * XDIM + c]; }
    if (i < NKV * G3) { int c = i / G3, o = i % G3; g_WihkT[i] = Wih[o * XDIM + ND + c]; }
    if (i < NQ * G3)  { int e = i / G3, o = i % G3; g_WhhT[i]  = Whh[o * NQ + e]; }
    if (i < NQ * NH)  { int q = i / NH, h = i % NH; g_W1T[i]   = W1[h * NQ + q]; }
}

// ---------------- gk = knowledge @ Wih_k^T + bih (iteration-invariant) ----------------
__global__ void k_gk(const float* __restrict__ kn, const float* __restrict__ bih) {
    __shared__ float knS[NKV];
    int row = blockIdx.x;            // b*36 + l
    int t = threadIdx.x;
    if (t < NKV) knS[t] = kn[row * NKV + t];
    __syncthreads();
    if (t < G3) {
        float acc = bih[t];
        #pragma unroll 4
        for (int c = 0; c < NKV; c++) acc += knS[c] * g_WihkT[c * G3 + t];
        g_gk[row * G3 + t] = acc;
    }
}

// ---------------- per-iteration projection vector w[b, 0:512] ----------------
// w = (1/6) * W_k_ctx^T @ (W_q^T @ sum_i LN(slots[b,i,:]))
__global__ void k_w(const float* __restrict__ slots, int bstride,
                    const float* __restrict__ lng, const float* __restrict__ lnb,
                    const float* __restrict__ Wq, const float* __restrict__ Wk) {
    int b = blockIdx.x;
    int t = threadIdx.x, lane = t & 31, wid = t >> 5;
    __shared__ float lnS[NQ * NQ];
    __shared__ float lnsum[NQ];
    __shared__ float qsum[NQ];
    const float* sp = slots + (size_t)bstride * b;
    // LayerNorm rows (one warp per row)
    for (int i = wid; i < NQ; i += 8) {
        float v1 = (lane < NQ)      ? sp[i * NQ + lane]      : 0.f;
        float v2 = (lane < NQ - 32) ? sp[i * NQ + lane + 32] : 0.f;
        float s = v1 + v2;
        for (int o = 16; o; o >>= 1) s += __shfl_xor_sync(~0u, s, o);
        float mu = s * (1.f / 36.f);
        float d1 = (lane < NQ) ? (v1 - mu) : 0.f;
        float d2 = (lane < NQ - 32) ? (v2 - mu) : 0.f;
        float vv = d1 * d1 + d2 * d2;
        for (int o = 16; o; o >>= 1) vv += __shfl_xor_sync(~0u, vv, o);
        float inv = rsqrtf(vv * (1.f / 36.f) + 1e-5f);
        if (lane < NQ)      lnS[i * NQ + lane]      = d1 * inv * lng[lane] + lnb[lane];
        if (lane < NQ - 32) lnS[i * NQ + lane + 32] = d2 * inv * lng[lane + 32] + lnb[lane + 32];
    }
    __syncthreads();
    if (t < NQ) {
        float s = 0.f;
        for (int i = 0; i < NQ; i++) s += lnS[i * NQ + t];
        lnsum[t] = s;
    }
    __syncthreads();
    if (t < NQ) {
        float s = 0.f;
        #pragma unroll 4
        for (int e = 0; e < NQ; e++) s += lnsum[e] * Wq[t * NQ + e];
        qsum[t] = s;
    }
    __syncthreads();
    for (int c = t; c < ND; c += blockDim.x) {
        float s = 0.f;
        #pragma unroll 4
        for (int d = 0; d < NQ; d++) s += qsum[d] * Wk[d * CKDIM + c];
        g_w[b * ND + c] = s * (1.f / 6.f);   // scale = 36^-0.5 folded in
    }
}

// ---------------- pass 1 over context: dots(iter0) + csumW ----------------
__global__ __launch_bounds__(128) void k_c(const float* __restrict__ ctx,
                                           float* __restrict__ dots0) {
    int v = blockIdx.x, b = blockIdx.y;
    int t = threadIdx.x, lane = t & 31, wid = t >> 5;
    __shared__ float red[4];
    __shared__ float csumS[ND];
    float4 acc = make_float4(0.f, 0.f, 0.f, 0.f);
    const float4* wb = (const float4*)(g_w + b * ND);
    float4 w4 = wb[t];
    for (int l = 0; l < NL; l++) {
        const float4* p = (const float4*)ctx + (size_t)((b * NL + l) * NV + v) * (ND / 4);
        float4 c = p[t];
        acc.x += c.x; acc.y += c.y; acc.z += c.z; acc.w += c.w;
        float pp = c.x * w4.x + c.y * w4.y + c.z * w4.z + c.w * w4.w;
        for (int o = 16; o; o >>= 1) pp += __shfl_xor_sync(~0u, pp, o);
        if (lane == 0) red[wid] = pp;
        __syncthreads();
        if (t == 0) dots0[(b * NL + l) * NV + v] = red[0] + red[1] + red[2] + red[3];
        __syncthreads();
    }
    ((float4*)csumS)[t] = acc;
    __syncthreads();
    if (t < G3) {
        float s = 0.f;
        #pragma unroll 4
        for (int c = 0; c < ND; c++) s += csumS[c] * g_WihuT[c * G3 + t];
        g_csumW[(b * NV + v) * G3 + t] = s;
    }
}

// ---------------- in-place softmax over views (iter0) ----------------
__global__ void k_sm(float* __restrict__ a) {
    int row = blockIdx.x;
    int lane = threadIdx.x;
    float x1 = (lane < NV)      ? a[row * NV + lane]      : -1e30f;
    float x2 = (lane + 32 < NV) ? a[row * NV + lane + 32] : -1e30f;
    float m = fmaxf(x1, x2);
    for (int o = 16; o; o >>= 1) m = fmaxf(m, __shfl_xor_sync(~0u, m, o));
    float e1 = (lane < NV) ? expf(x1 - m) : 0.f;
    float e2 = (lane + 32 < NV) ? expf(x2 - m) : 0.f;
    float s = e1 + e2;
    for (int o = 16; o; o >>= 1) s += __shfl_xor_sync(~0u, s, o);
    float inv = 1.f / s;
    if (lane < NV)      a[row * NV + lane]      = e1 * inv;
    if (lane + 32 < NV) a[row * NV + lane + 32] = e2 * inv;
}

// ---------------- iters 1,2: dots + fused softmax ----------------
__global__ __launch_bounds__(128) void k_d(const float* __restrict__ ctx,
                                           float* __restrict__ attnT) {
    int l = blockIdx.x, b = blockIdx.y;
    int t = threadIdx.x, lane = t & 31, wp = t >> 5;
    __shared__ float wS[ND];
    __shared__ float dotsS[NV];
    for (int c = t; c < ND; c += 128) wS[c] = g_w[b * ND + c];
    __syncthreads();
    const float4* base = (const float4*)ctx + (size_t)((b * NL + l) * NV) * (ND / 4);
    const float4* wS4 = (const float4*)wS;
    for (int v = wp; v < NV; v += 4) {
        float p = 0.f;
        #pragma unroll
        for (int k = 0; k < 4; k++) {
            float4 c = base[v * (ND / 4) + lane + 32 * k];
            float4 w = wS4[lane + 32 * k];
            p += c.x * w.x + c.y * w.y + c.z * w.z + c.w * w.w;
        }
        for (int o = 16; o; o >>= 1) p += __shfl_xor_sync(~0u, p, o);
        if (lane == 0) dotsS[v] = p;
    }
    __syncthreads();
    if (wp == 0) {
        float x1 = (lane < NV)      ? dotsS[lane]      : -1e30f;
        float x2 = (lane + 32 < NV) ? dotsS[lane + 32] : -1e30f;
        float m = fmaxf(x1, x2);
        for (int o = 16; o; o >>= 1) m = fmaxf(m, __shfl_xor_sync(~0u, m, o));
        float e1 = (lane < NV) ? expf(x1 - m) : 0.f;
        float e2 = (lane + 32 < NV) ? expf(x2 - m) : 0.f;
        float s = e1 + e2;
        for (int o = 16; o; o >>= 1) s += __shfl_xor_sync(~0u, s, o);
        float inv = 1.f / s;
        float* arow = attnT + (b * NL + l) * NV;
        if (lane < NV)      arow[lane]      = e1 * inv;
        if (lane + 32 < NV) arow[lane + 32] = e2 * inv;
    }
}

// ---------------- fused GRU + LN + MLP per batch element ----------------
__global__ __launch_bounds__(512) void k_g(const float* __restrict__ attnT,
                                           const float* __restrict__ slots_prev, int bstride,
                                           const float* __restrict__ bhh,
                                           const float* __restrict__ lnfg, const float* __restrict__ lnfb,
                                           const float* __restrict__ b1,
                                           const float* __restrict__ W2, const float* __restrict__ b2,
                                           float* __restrict__ slots_out) {
    extern __shared__ float sm[];
    float* attnS = sm;              // 1296
    float* hpS   = attnS + 1296;    // 1296
    float* gxS   = hpS + 1296;      // 3888
    float* ghS   = gxS + 3888;      // 3888
    float* gnewS = ghS + 3888;      // 1296
    float* ffS   = gnewS + 1296;    // 1296
    float* hidS  = ffS + 1296;      // 36*512
    float* W2S   = hidS + NQ * NH;  // 36*513 (padded, conflict-free)
    int b = blockIdx.x;
    int t = threadIdx.x, lane = t & 31, wp = t >> 5;

    for (int i = t; i < 1296; i += 512) {
        attnS[i] = attnT[b * 1296 + i];
        hpS[i] = slots_prev[(size_t)bstride * b + i];
    }
    for (int i = t; i < NQ * NH; i += 512) {
        int q = i / NH, h = i % NH;
        W2S[q * 513 + h] = W2[i];
    }
    __syncthreads();

    // gx = gk + attn @ csumW ; gh = bhh + hp @ Whh^T
    for (int idx = t; idx < NQ * G3; idx += 512) {
        int i = idx / G3, o = idx % G3;
        float gx = g_gk[(b * NQ + i) * G3 + o];
        const float* cw = g_csumW + b * NQ * G3 + o;
        const float* ar = attnS + i * NQ;
        #pragma unroll 4
        for (int j = 0; j < NQ; j++) gx += ar[j] * cw[j * G3];
        gxS[idx] = gx;
        float gh = bhh[o];
        const float* hr = hpS + i * NQ;
        #pragma unroll 4
        for (int e = 0; e < NQ; e++) gh += hr[e] * g_WhhT[e * G3 + o];
        ghS[idx] = gh;
    }
    __syncthreads();

    // GRU gates (r,z,n order)
    for (int idx = t; idx < 1296; idx += 512) {
        int i = idx / NQ, qq = idx % NQ;
        float r = 1.f / (1.f + expf(-(gxS[i * G3 + qq] + ghS[i * G3 + qq])));
        float z = 1.f / (1.f + expf(-(gxS[i * G3 + NQ + qq] + ghS[i * G3 + NQ + qq])));
        float n = tanhf(gxS[i * G3 + 2 * NQ + qq] + r * ghS[i * G3 + 2 * NQ + qq]);
        gnewS[idx] = (1.f - z) * n + z * hpS[idx];
    }
    __syncthreads();

    // LayerNorm rows of gnew
    for (int i = wp; i < NQ; i += 16) {
        float v1 = (lane < NQ) ? gnewS[i * NQ + lane] : 0.f;
        float v2 = (lane < 4)  ? gnewS[i * NQ + lane + 32] : 0.f;
        float s = v1 + v2;
        for (int o = 16; o; o >>= 1) s += __shfl_xor_sync(~0u, s, o);
        float mu = s * (1.f / 36.f);
        float d1 = (lane < NQ) ? (v1 - mu) : 0.f;
        float d2 = (lane < 4)  ? (v2 - mu) : 0.f;
        float vv = d1 * d1 + d2 * d2;
        for (int o = 16; o; o >>= 1) vv += __shfl_xor_sync(~0u, vv, o);
        float inv = rsqrtf(vv * (1.f / 36.f) + 1e-5f);
        if (lane < NQ) ffS[i * NQ + lane]      = d1 * inv * lnfg[lane] + lnfb[lane];
        if (lane < 4)  ffS[i * NQ + lane + 32] = d2 * inv * lnfg[lane + 32] + lnfb[lane + 32];
    }
    __syncthreads();

    // hidden = relu(ff @ W1^T + b1): thread t == h
    {
        int h = t;
        float w1r[NQ];
        #pragma unroll
        for (int q = 0; q < NQ; q++) w1r[q] = g_W1T[q * NH + h];
        float bb = b1[h];
        for (int i = 0; i < NQ; i++) {
            float acc = bb;
            #pragma unroll 4
            for (int q = 0; q < NQ; q++) acc += ffS[i * NQ + q] * w1r[q];
            hidS[i * NH + h] = fmaxf(acc, 0.f);
        }
    }
    __syncthreads();

    // out = gnew + hidden @ W2^T + b2
    for (int idx = t; idx < 1296; idx += 512) {
        int i = idx / NQ, qq = idx % NQ;
        float acc = b2[qq];
        const float* hr = hidS + i * NH;
        const float* wr = W2S + qq * 513;
        #pragma unroll 4
        for (int h = 0; h < NH; h++) acc += hr[h] * wr[h];
        slots_out[b * 1296 + idx] = gnewS[idx] + acc;
    }
}

static const int KG_SMEM = (1296 + 1296 + 3888 + 3888 + 1296 + 1296 + 36 * 512 + 36 * 513) * 4;

extern "C" void kernel_launch(void* const* d_in, const int* in_sizes, int n_in,
                              void* d_out, int out_size) {
    const float* ctx  = (const float*)d_in[1];
    const float* kn   = (const float*)d_in[4];
    const float* pano = (const float*)d_in[5];
    const float* Wq   = (const float*)d_in[6];
    const float* Wk   = (const float*)d_in[7];
    const float* Wih  = (const float*)d_in[8];
    const float* Whh  = (const float*)d_in[9];
    const float* bih  = (const float*)d_in[10];
    const float* bhh  = (const float*)d_in[11];
    const float* lsg  = (const float*)d_in[12];
    const float* lsb  = (const float*)d_in[13];
    const float* lfg  = (const float*)d_in[14];
    const float* lfb  = (const float*)d_in[15];
    const float* W1   = (const float*)d_in[16];
    const float* b1   = (const float*)d_in[17];
    const float* W2   = (const float*)d_in[18];
    const float* b2   = (const float*)d_in[19];

    float* out = (float*)d_out;
    float* slots = out;                       // [B,36,36]
    // attn slabs: [3,B,36,36] right after slots

    cudaFuncSetAttribute(k_g, cudaFuncAttributeMaxDynamicSharedMemorySize, KG_SMEM);

    k_transpose<<<(ND * G3 + 255) / 256, 256>>>(Wih, Whh, W1);
    k_gk<<<NB * NL, 128>>>(kn, bih);

    for (int it = 0; it < 3; it++) {
        float* attnT = out + NB * NL * NV * (1 + it);
        const float* sp = it ? (const float*)slots : pano;
        int bs = it ? 1296 : 0;
        k_w<<<NB, 256>>>(sp, bs, lsg, lsb, Wq, Wk);
        if (it == 0) {
            k_c<<<dim3(NV, NB), 128>>>(ctx, attnT);
            k_sm<<<NB * NL, 32>>>(attnT);
        } else {
            k_d<<<dim3(NL, NB), 128>>>(ctx, attnT);
        }
        k_g<<<NB, 512, KG_SMEM>>>(attnT, sp, bs, bhh, lfg, lfb, b1, W2, b2, slots);
    }
}

// round 3
// speedup vs baseline: 1.0702x; 1.0702x over previous
#include <cuda_runtime.h>

#define NB 128
#define NL 36
#define NV 36
#define ND 512
#define NKV 112
#define NQ 36
#define NH 512
#define G3 108
#define CKDIM 812   // D + KD
#define XDIM 624    // D + KV

typedef unsigned long long u64;

__device__ __forceinline__ void ffma2(u64& d, u64 a, u64 b) {
    asm("fma.rn.f32x2 %0, %1, %2, %0;" : "+l"(d) : "l"(a), "l"(b));
}
__device__ __forceinline__ float hsum2(u64 v) {
    float lo, hi;
    asm("mov.b64 {%0,%1}, %2;" : "=f"(lo), "=f"(hi) : "l"(v));
    return lo + hi;
}

// ---------------- scratch (device globals; no allocs allowed) ----------------
__device__ float g_csumWT[NB * G3 * NQ];  // [b][o][v]: ((sum_l ctx) @ Wih_u^T)^T
__device__ float g_gk[NB * NL * G3];      // knowledge @ Wih_k^T + bih
__device__ float g_w[NB * ND];            // per-iteration projection vector
__device__ float g_WihuO[G3 * ND];        // Wih rows, first 512 cols (row-major copy)
__device__ float g_WihkT[NKV * G3];       // transposed knowledge part

// ---------------- weight prep ----------------
__global__ void k_prep(const float* __restrict__ Wih) {
    int i = blockIdx.x * blockDim.x + threadIdx.x;
    if (i < G3 * ND)  { int o = i / ND, c = i % ND; g_WihuO[i] = Wih[o * XDIM + c]; }
    if (i < NKV * G3) { int c = i / G3, o = i % G3; g_WihkT[i] = Wih[o * XDIM + ND + c]; }
}

// ---------------- gk = knowledge @ Wih_k^T + bih (iteration-invariant) ----------------
__global__ void k_gk(const float* __restrict__ kn, const float* __restrict__ bih) {
    __shared__ float knS[NKV];
    int row = blockIdx.x;            // b*36 + l
    int t = threadIdx.x;
    if (t < NKV) knS[t] = kn[row * NKV + t];
    __syncthreads();
    if (t < G3) {
        float acc = bih[t];
        #pragma unroll 4
        for (int c = 0; c < NKV; c++) acc += knS[c] * g_WihkT[c * G3 + t];
        g_gk[row * G3 + t] = acc;
    }
}

// ---------------- per-iteration projection vector w[b, 0:512] ----------------
__global__ void k_w(const float* __restrict__ slots, int bstride,
                    const float* __restrict__ lng, const float* __restrict__ lnb,
                    const float* __restrict__ Wq, const float* __restrict__ Wk) {
    int b = blockIdx.x;
    int t = threadIdx.x, lane = t & 31, wid = t >> 5;
    __shared__ float lnS[NQ * NQ];
    __shared__ float lnsum[NQ];
    __shared__ float qsum[NQ];
    const float* sp = slots + (size_t)bstride * b;
    for (int i = wid; i < NQ; i += 8) {
        float v1 = (lane < NQ)      ? sp[i * NQ + lane]      : 0.f;
        float v2 = (lane < NQ - 32) ? sp[i * NQ + lane + 32] : 0.f;
        float s = v1 + v2;
        for (int o = 16; o; o >>= 1) s += __shfl_xor_sync(~0u, s, o);
        float mu = s * (1.f / 36.f);
        float d1 = (lane < NQ) ? (v1 - mu) : 0.f;
        float d2 = (lane < NQ - 32) ? (v2 - mu) : 0.f;
        float vv = d1 * d1 + d2 * d2;
        for (int o = 16; o; o >>= 1) vv += __shfl_xor_sync(~0u, vv, o);
        float inv = rsqrtf(vv * (1.f / 36.f) + 1e-5f);
        if (lane < NQ)      lnS[i * NQ + lane]      = d1 * inv * lng[lane] + lnb[lane];
        if (lane < NQ - 32) lnS[i * NQ + lane + 32] = d2 * inv * lng[lane + 32] + lnb[lane + 32];
    }
    __syncthreads();
    if (t < NQ) {
        float s = 0.f;
        for (int i = 0; i < NQ; i++) s += lnS[i * NQ + t];
        lnsum[t] = s;
    }
    __syncthreads();
    if (t < NQ) {
        float s = 0.f;
        #pragma unroll 4
        for (int e = 0; e < NQ; e++) s += lnsum[e] * Wq[t * NQ + e];
        qsum[t] = s;
    }
    __syncthreads();
    for (int c = t; c < ND; c += blockDim.x) {
        float s = 0.f;
        #pragma unroll 4
        for (int d = 0; d < NQ; d++) s += qsum[d] * Wk[d * CKDIM + c];
        g_w[b * ND + c] = s * (1.f / 6.f);   // scale = 36^-0.5 folded in
    }
}

// ---------------- pass 1 over context: dots(iter0) + csumW^T ----------------
// block (v, b); deferred reductions: zero syncs inside the l-loop.
__global__ __launch_bounds__(128) void k_c(const float* __restrict__ ctx,
                                           float* __restrict__ dots0) {
    int v = blockIdx.x, b = blockIdx.y;
    int t = threadIdx.x, lane = t & 31, wid = t >> 5;
    __shared__ float redS[NL * 4];
    __shared__ float csumS[ND];
    float4 acc = make_float4(0.f, 0.f, 0.f, 0.f);
    const float4* wb = (const float4*)(g_w + b * ND);
    float4 w4 = wb[t];
    float pp[NL];
    const float4* base = (const float4*)ctx + (size_t)(b * NL * NV + v) * (ND / 4) + t;
    #pragma unroll
    for (int l = 0; l < NL; l++) {
        float4 c = base[(size_t)l * NV * (ND / 4)];
        acc.x += c.x; acc.y += c.y; acc.z += c.z; acc.w += c.w;
        pp[l] = c.x * w4.x + c.y * w4.y + c.z * w4.z + c.w * w4.w;
    }
    #pragma unroll
    for (int l = 0; l < NL; l++) {
        float r = pp[l];
        for (int o = 16; o; o >>= 1) r += __shfl_xor_sync(~0u, r, o);
        if (lane == 0) redS[l * 4 + wid] = r;
    }
    ((float4*)csumS)[t] = acc;
    __syncthreads();
    if (t < NL)
        dots0[(b * NL + t) * NV + v] = redS[t * 4 + 0] + redS[t * 4 + 1] + redS[t * 4 + 2] + redS[t * 4 + 3];
    if (t < G3) {
        int o = t;
        u64 a0 = 0, a1 = 0;
        const ulonglong2* cs = (const ulonglong2*)csumS;
        const ulonglong2* wr = (const ulonglong2*)(g_WihuO + o * ND);
        #pragma unroll 16
        for (int c = 0; c < ND / 4; c++) {
            ulonglong2 u = cs[c];
            ulonglong2 w = wr[c];
            ffma2(a0, u.x, w.x);
            ffma2(a1, u.y, w.y);
        }
        g_csumWT[b * G3 * NQ + o * NQ + v] = hsum2(a0) + hsum2(a1);
    }
}

// ---------------- in-place softmax over views (iter0) ----------------
__global__ void k_sm(float* __restrict__ a) {
    int row = blockIdx.x;
    int lane = threadIdx.x;
    float x1 = a[row * NV + lane];
    float x2 = (lane + 32 < NV) ? a[row * NV + lane + 32] : -1e30f;
    float m = fmaxf(x1, x2);
    for (int o = 16; o; o >>= 1) m = fmaxf(m, __shfl_xor_sync(~0u, m, o));
    float e1 = expf(x1 - m);
    float e2 = (lane + 32 < NV) ? expf(x2 - m) : 0.f;
    float s = e1 + e2;
    for (int o = 16; o; o >>= 1) s += __shfl_xor_sync(~0u, s, o);
    float inv = 1.f / s;
    a[row * NV + lane] = e1 * inv;
    if (lane + 32 < NV) a[row * NV + lane + 32] = e2 * inv;
}

// ---------------- iters 1,2: streaming dots + fused softmax ----------------
// block = 72 contiguous rows (2 softmax groups); warp handles 9 rows.
__global__ __launch_bounds__(256) void k_d(const float* __restrict__ ctx,
                                           float* __restrict__ attnT) {
    int tile = blockIdx.x, b = blockIdx.y;       // tile 0..17
    int t = threadIdx.x, lane = t & 31, w = t >> 5;
    __shared__ float dotsS[72];
    const float4* wb = (const float4*)(g_w + b * ND);
    float4 w0 = wb[lane], w1 = wb[lane + 32], w2 = wb[lane + 64], w3 = wb[lane + 96];
    int row0 = tile * 72 + w * 9;
    const float4* base = (const float4*)ctx + ((size_t)b * (NL * NV) + row0) * (ND / 4);
    float pp[9];
    #pragma unroll
    for (int r = 0; r < 9; r++) {
        const float4* p = base + r * (ND / 4);
        float4 c0 = p[lane], c1 = p[lane + 32], c2 = p[lane + 64], c3 = p[lane + 96];
        pp[r] = c0.x * w0.x + c0.y * w0.y + c0.z * w0.z + c0.w * w0.w
              + c1.x * w1.x + c1.y * w1.y + c1.z * w1.z + c1.w * w1.w
              + c2.x * w2.x + c2.y * w2.y + c2.z * w2.z + c2.w * w2.w
              + c3.x * w3.x + c3.y * w3.y + c3.z * w3.z + c3.w * w3.w;
    }
    #pragma unroll
    for (int r = 0; r < 9; r++) {
        float v = pp[r];
        for (int o = 16; o; o >>= 1) v += __shfl_xor_sync(~0u, v, o);
        if (lane == 0) dotsS[w * 9 + r] = v;
    }
    __syncthreads();
    if (w < 2) {
        float x1 = dotsS[w * 36 + lane];
        float x2 = (lane < 4) ? dotsS[w * 36 + lane + 32] : -1e30f;
        float m = fmaxf(x1, x2);
        for (int o = 16; o; o >>= 1) m = fmaxf(m, __shfl_xor_sync(~0u, m, o));
        float e1 = expf(x1 - m);
        float e2 = (lane < 4) ? expf(x2 - m) : 0.f;
        float s = e1 + e2;
        for (int o = 16; o; o >>= 1) s += __shfl_xor_sync(~0u, s, o);
        float inv = 1.f / s;
        int l = tile * 2 + w;
        float* arow = attnT + (b * NL + l) * NV;
        arow[lane] = e1 * inv;
        if (lane < 4) arow[lane + 32] = e2 * inv;
    }
}

// ---------------- fused GRU + LN + MLP per batch element (f32x2 + LDS.128) ----------------
__global__ __launch_bounds__(512) void k_g(const float* __restrict__ attnT,
                                           const float* __restrict__ slots_prev, int bstride,
                                           const float* __restrict__ Whh,
                                           const float* __restrict__ bhh,
                                           const float* __restrict__ lnfg, const float* __restrict__ lnfb,
                                           const float* __restrict__ W1, const float* __restrict__ b1,
                                           const float* __restrict__ W2, const float* __restrict__ b2,
                                           float* __restrict__ slots_out) {
    extern __shared__ float sm[];
    float* attnS = sm;              // 1296
    float* hpS   = attnS + 1296;    // 1296
    float* gxS   = hpS + 1296;      // 3888
    float* ghS   = gxS + 3888;      // 3888
    float* gnewS = ghS + 3888;      // 1296
    float* ffS   = gnewS + 1296;    // 1296
    float* hidS  = ffS + 1296;      // 36*512
    float* W2S   = hidS + NQ * NH;  // 36*516 (pad 516: 16B-aligned rows, conflict-free)
    int b = blockIdx.x;
    int t = threadIdx.x, lane = t & 31, wp = t >> 5;

    for (int i = t; i < 1296; i += 512) {
        attnS[i] = attnT[b * 1296 + i];
        hpS[i] = slots_prev[(size_t)bstride * b + i];
    }
    for (int i = t; i < NQ * NH; i += 512) {
        int q = i >> 9, c = i & 511;
        W2S[q * 516 + c] = W2[i];
    }
    __syncthreads();

    // gx = gk + attn @ csumW^T ; gh = bhh + hp @ Whh^T   (rows as ulonglong2)
    for (int idx = t; idx < NQ * G3; idx += 512) {
        int i = idx / G3, o = idx - i * G3;
        u64 a0 = 0, a1 = 0;
        const ulonglong2* ar = (const ulonglong2*)(attnS + i * NQ);
        const ulonglong2* cw = (const ulonglong2*)(g_csumWT + b * G3 * NQ + o * NQ);
        #pragma unroll
        for (int c = 0; c < 9; c++) {
            ulonglong2 u = ar[c], v = cw[c];
            ffma2(a0, u.x, v.x);
            ffma2(a1, u.y, v.y);
        }
        gxS[idx] = g_gk[(b * NQ + i) * G3 + o] + hsum2(a0) + hsum2(a1);
        u64 h0 = 0, h1 = 0;
        const ulonglong2* hr = (const ulonglong2*)(hpS + i * NQ);
        const ulonglong2* wh = (const ulonglong2*)(Whh + o * NQ);
        #pragma unroll
        for (int c = 0; c < 9; c++) {
            ulonglong2 u = hr[c], v = wh[c];
            ffma2(h0, u.x, v.x);
            ffma2(h1, u.y, v.y);
        }
        ghS[idx] = bhh[o] + hsum2(h0) + hsum2(h1);
    }
    __syncthreads();

    // GRU gates (r,z,n order)
    for (int idx = t; idx < 1296; idx += 512) {
        int i = idx / NQ, qq = idx - i * NQ;
        float r = 1.f / (1.f + expf(-(gxS[i * G3 + qq] + ghS[i * G3 + qq])));
        float z = 1.f / (1.f + expf(-(gxS[i * G3 + NQ + qq] + ghS[i * G3 + NQ + qq])));
        float n = tanhf(gxS[i * G3 + 2 * NQ + qq] + r * ghS[i * G3 + 2 * NQ + qq]);
        gnewS[idx] = (1.f - z) * n + z * hpS[idx];
    }
    __syncthreads();

    // LayerNorm rows of gnew
    for (int i = wp; i < NQ; i += 16) {
        float v1 = (lane < NQ) ? gnewS[i * NQ + lane] : 0.f;
        float v2 = (lane < 4)  ? gnewS[i * NQ + lane + 32] : 0.f;
        float s = v1 + v2;
        for (int o = 16; o; o >>= 1) s += __shfl_xor_sync(~0u, s, o);
        float mu = s * (1.f / 36.f);
        float d1 = (lane < NQ) ? (v1 - mu) : 0.f;
        float d2 = (lane < 4)  ? (v2 - mu) : 0.f;
        float vv = d1 * d1 + d2 * d2;
        for (int o = 16; o; o >>= 1) vv += __shfl_xor_sync(~0u, vv, o);
        float inv = rsqrtf(vv * (1.f / 36.f) + 1e-5f);
        if (lane < NQ) ffS[i * NQ + lane]      = d1 * inv * lnfg[lane] + lnfb[lane];
        if (lane < 4)  ffS[i * NQ + lane + 32] = d2 * inv * lnfg[lane + 32] + lnfb[lane + 32];
    }
    __syncthreads();

    // hidden = relu(ff @ W1^T + b1): thread t = h; W1 row preloaded from global
    {
        int h = t;
        ulonglong2 w1p[9];
        const ulonglong2* wr = (const ulonglong2*)(W1 + h * NQ);
        #pragma unroll
        for (int c = 0; c < 9; c++) w1p[c] = wr[c];
        float bb = b1[h];
        for (int i = 0; i < NQ; i++) {
            u64 a0 = 0, a1 = 0;
            const ulonglong2* fr = (const ulonglong2*)(ffS + i * NQ);
            #pragma unroll
            for (int c = 0; c < 9; c++) {
                ulonglong2 u = fr[c];
                ffma2(a0, u.x, w1p[c].x);
                ffma2(a1, u.y, w1p[c].y);
            }
            hidS[i * NH + h] = fmaxf(bb + hsum2(a0) + hsum2(a1), 0.f);
        }
    }
    __syncthreads();

    // out = gnew + hidden @ W2^T + b2
    for (int idx = t; idx < 1296; idx += 512) {
        int i = idx / NQ, qq = idx - i * NQ;
        u64 a0 = 0, a1 = 0;
        const ulonglong2* hr = (const ulonglong2*)(hidS + i * NH);
        const ulonglong2* wr = (const ulonglong2*)(W2S + qq * 516);
        #pragma unroll 8
        for (int c = 0; c < NH / 4; c++) {
            ulonglong2 u = hr[c], v = wr[c];
            ffma2(a0, u.x, v.x);
            ffma2(a1, u.y, v.y);
        }
        slots_out[b * 1296 + idx] = gnewS[idx] + b2[qq] + hsum2(a0) + hsum2(a1);
    }
}

static const int KG_SMEM = (1296 + 1296 + 3888 + 3888 + 1296 + 1296 + NQ * NH + NQ * 516) * 4;

extern "C" void kernel_launch(void* const* d_in, const int* in_sizes, int n_in,
                              void* d_out, int out_size) {
    const float* ctx  = (const float*)d_in[1];
    const float* kn   = (const float*)d_in[4];
    const float* pano = (const float*)d_in[5];
    const float* Wq   = (const float*)d_in[6];
    const float* Wk   = (const float*)d_in[7];
    const float* Wih  = (const float*)d_in[8];
    const float* Whh  = (const float*)d_in[9];
    const float* bih  = (const float*)d_in[10];
    const float* bhh  = (const float*)d_in[11];
    const float* lsg  = (const float*)d_in[12];
    const float* lsb  = (const float*)d_in[13];
    const float* lfg  = (const float*)d_in[14];
    const float* lfb  = (const float*)d_in[15];
    const float* W1   = (const float*)d_in[16];
    const float* b1   = (const float*)d_in[17];
    const float* W2   = (const float*)d_in[18];
    const float* b2   = (const float*)d_in[19];

    float* out = (float*)d_out;
    float* slots = out;                       // [B,36,36]
    // attn slabs: [3,B,36,36] right after slots

    cudaFuncSetAttribute(k_g, cudaFuncAttributeMaxDynamicSharedMemorySize, KG_SMEM);

    k_prep<<<(G3 * ND + 255) / 256, 256>>>(Wih);
    k_gk<<<NB * NL, 128>>>(kn, bih);

    for (int it = 0; it < 3; it++) {
        float* attnT = out + NB * NL * NV * (1 + it);
        const float* sp = it ? (const float*)slots : pano;
        int bs = it ? 1296 : 0;
        k_w<<<NB, 256>>>(sp, bs, lsg, lsb, Wq, Wk);
        if (it == 0) {
            k_c<<<dim3(NV, NB), 128>>>(ctx, attnT);
            k_sm<<<NB * NL, 32>>>(attnT);
        } else {
            k_d<<<dim3(18, NB), 256>>>(ctx, attnT);
        }
        k_g<<<NB, 512, KG_SMEM>>>(attnT, sp, bs, Whh, bhh, lfg, lfb, W1, b1, W2, b2, slots);
    }
}